// round 13
// baseline (speedup 1.0000x reference)
#include <cuda_runtime.h>
#include <cuda_fp16.h>
#include <cstdint>

#define DD 128
#define HSTR 136                 // smem half-row stride (136 halves = 272B ≡ 4 banks)
#define MAXM 200000
#define MAXE 650000
#define MAXR 256
#define MAXB 8

// -------- scratch (static device memory; no allocs allowed) --------
__device__ __half g_pack[(size_t)MAXM * 256]; // per row: [0:128)=Hs fp16, [128:256)=hidden fp16
__device__ float  g_agg[(size_t)MAXM * DD];   // aggregation output (written once per recv node)
__device__ int    g_deg[MAXM];                // receive flags (written for ALL nodes each launch)
__device__ float  g_Rr[MAXR * DD];            // rela_embed @ Wr^T
__device__ float  g_Qq[MAXB * DD];            // query @ Wqr^T + b
__device__ float  g_Wf[DD * DD];              // mlp2 @ mlp1, natural [n][k]
__device__ float  g_bf[DD];                   // mlp2 @ b1 + b2
__device__ __half g_WsH[DD * DD];             // fp16(Ws_attn_w) [n][k]
__device__ __half g_WfH[DD * DD];             // fp16 hi part of Wf [n][k]
__device__ __half g_WfL[DD * DD];             // fp16 lo part of Wf [n][k]
// CSR scratch
__device__ int    g_cnt[MAXM];
__device__ int    g_off[MAXM + 1];
__device__ int    g_cur[MAXM];
__device__ int    g_bsum[256];
__device__ int    g_eidx[MAXE];

__device__ __forceinline__ uint32_t h2u(__half2 h) {
    return *reinterpret_cast<uint32_t*>(&h);
}

// m16n8k16 f16 MMA, f32 accum (baseline PTX sm_80+)
__device__ __forceinline__ void mma16816(float* d, const uint32_t* a, uint32_t b0, uint32_t b1) {
    asm volatile(
        "mma.sync.aligned.m16n8k16.row.col.f32.f16.f16.f32 "
        "{%0,%1,%2,%3}, {%4,%5,%6,%7}, {%8,%9}, {%0,%1,%2,%3};"
        : "+f"(d[0]), "+f"(d[1]), "+f"(d[2]), "+f"(d[3])
        : "r"(a[0]), "r"(a[1]), "r"(a[2]), "r"(a[3]), "r"(b0), "r"(b1));
}

// ================= prep: Wf (natural [n][k]), bf, Rr, Qq =================
__global__ void prep_kernel(const float* __restrict__ mlp1_w, const float* __restrict__ mlp1_b,
                            const float* __restrict__ mlp2_w, const float* __restrict__ mlp2_b,
                            const float* __restrict__ rela,   const float* __restrict__ Wr,
                            const float* __restrict__ query,  const float* __restrict__ Wqr,
                            const float* __restrict__ Wqr_b,  int R)
{
    int t = threadIdx.x;
    int bx = blockIdx.x;
    if (bx < DD) {
        int i = bx;
        float acc = 0.f;
        for (int j = 0; j < DD; j++) acc += mlp2_w[i * DD + j] * mlp1_w[j * DD + t];
        g_Wf[i * DD + t] = acc;
        __shared__ float s[DD];
        s[t] = mlp2_w[i * DD + t] * mlp1_b[t];
        __syncthreads();
        if (t == 0) {
            float b = 0.f;
            for (int j = 0; j < DD; j++) b += s[j];
            g_bf[i] = b + mlp2_b[i];
        }
    } else if (bx < DD + R) {
        int r = bx - DD;
        float acc = 0.f;
        for (int d = 0; d < DD; d++) acc += rela[r * DD + d] * Wr[t * DD + d];
        g_Rr[r * DD + t] = acc;
    } else {
        int b = bx - DD - R;
        float acc = Wqr_b[t];
        for (int d = 0; d < DD; d++) acc += query[b * DD + d] * Wqr[t * DD + d];
        g_Qq[b * DD + t] = acc;
    }
}

// convert Ws -> fp16; Wf -> fp16 hi/lo split
__global__ void convert_kernel(const float* __restrict__ Ws) {
    int i = blockIdx.x * 256 + threadIdx.x;
    if (i >= DD * DD) return;
    g_WsH[i] = __float2half_rn(Ws[i]);
    float w = g_Wf[i];
    __half h = __float2half_rn(w);
    g_WfH[i] = h;
    g_WfL[i] = __float2half_rn(w - __half2float(h));
}

// ================= CSR build =================
__global__ void hist_k(const int4* __restrict__ edges, int E) {
    int e = blockIdx.x * 256 + threadIdx.x;
    if (e < E) atomicAdd(&g_cnt[edges[e].w], 1);
}

// block-local exclusive scan (1024 elems/block) -> g_off (local), g_bsum[b] = block total
__global__ void scan1_k(int M) {
    __shared__ int warpsums[8];
    int b = blockIdx.x, t = threadIdx.x;
    int base = b * 1024 + t * 4;
    int v[4];
    #pragma unroll
    for (int j = 0; j < 4; j++) v[j] = (base + j < M) ? g_cnt[base + j] : 0;
    int s = v[0] + v[1] + v[2] + v[3];
    int lane = t & 31, w = t >> 5;
    int ps = s;
    #pragma unroll
    for (int o = 1; o < 32; o <<= 1) {
        int n = __shfl_up_sync(0xffffffffu, ps, o);
        if (lane >= o) ps += n;
    }
    if (lane == 31) warpsums[w] = ps;
    __syncthreads();
    if (w == 0) {
        int ws = (lane < 8) ? warpsums[lane] : 0;
        #pragma unroll
        for (int o = 1; o < 8; o <<= 1) {
            int n = __shfl_up_sync(0xffffffffu, ws, o);
            if (lane >= o) ws += n;
        }
        if (lane < 8) warpsums[lane] = ws;
    }
    __syncthreads();
    int warpbase = (w > 0) ? warpsums[w - 1] : 0;
    int run = warpbase + ps - s;    // exclusive prefix for this thread
    #pragma unroll
    for (int j = 0; j < 4; j++) {
        if (base + j < M) g_off[base + j] = run;
        run += v[j];
    }
    if (t == 255) g_bsum[b] = warpbase + ps;
}

// scan the block sums (nb <= 256) in smem; also set g_off[M] = E
__global__ void scan2_k(int nb, int E, int M) {
    __shared__ int sh[256];
    int t = threadIdx.x;
    sh[t] = (t < nb) ? g_bsum[t] : 0;
    __syncthreads();
    if (t == 0) {
        int run = 0;
        for (int i = 0; i < nb; i++) { int v = sh[i]; sh[i] = run; run += v; }
        g_off[M] = E;
    }
    __syncthreads();
    if (t < nb) g_bsum[t] = sh[t];
}

// add block bases; copy to cursor
__global__ void scan3_k(int M) {
    int i = blockIdx.x * 256 + threadIdx.x;
    if (i < M) {
        int v = g_off[i] + g_bsum[i >> 10];
        g_off[i] = v;
        g_cur[i] = v;
    }
}

__global__ void scatter_k(const int4* __restrict__ edges, int E) {
    int e = blockIdx.x * 256 + threadIdx.x;
    if (e < E) {
        int pos = atomicAdd(&g_cur[edges[e].w], 1);
        g_eidx[pos] = e;
    }
}

// ================= GEMM1: pack = [fp16(hidden @ Ws^T) | fp16(hidden)] =================
#define SM1_BYTES ((128 + 64) * HSTR * 2)   // 52,224 B
__global__ __launch_bounds__(256, 2)
void gemm_h1(const float* __restrict__ A, const __half* __restrict__ W,
             __half* __restrict__ P, int M)
{
    extern __shared__ __half smh[];
    __half* sA = smh;                  // 128 x HSTR
    __half* sW = smh + 128 * HSTR;     // 64 x HSTR

    const int tid = threadIdx.x;
    const int mb = blockIdx.x >> 1;
    const int nb = blockIdx.x & 1;
    const int m0 = mb * 128;
    const int n0 = nb * 64;

    const float4* A4 = reinterpret_cast<const float4*>(A);
    #pragma unroll
    for (int i = tid; i < 128 * 32; i += 256) {
        int row = i >> 5, c4 = i & 31;
        int gr = m0 + row;
        float4 v = make_float4(0.f, 0.f, 0.f, 0.f);
        if (gr < M) v = A4[(size_t)gr * 32 + c4];
        uint2 u = make_uint2(h2u(__floats2half2_rn(v.x, v.y)),
                             h2u(__floats2half2_rn(v.z, v.w)));
        *reinterpret_cast<uint2*>(&sA[row * HSTR + c4 * 4]) = u;
    }
    const uint4* W4 = reinterpret_cast<const uint4*>(W);
    #pragma unroll
    for (int i = tid; i < 64 * 16; i += 256) {
        int row = i >> 4, c8 = i & 15;
        *reinterpret_cast<uint4*>(&sW[row * HSTR + c8 * 8]) = W4[(size_t)(n0 + row) * 16 + c8];
    }
    __syncthreads();

    const int lane = tid & 31;
    const int wid = tid >> 5;
    const int g = lane >> 2;
    const int t4 = lane & 3;
    const int wm = (wid >> 1) * 32;
    const int wn = (wid & 1) * 32;

    const __half* aB = sA + (wm + g) * HSTR;
    const __half* bB = sW + (wn + g) * HSTR;

    float acc[2][4][4];
    #pragma unroll
    for (int mt = 0; mt < 2; mt++)
        #pragma unroll
        for (int nt = 0; nt < 4; nt++)
            #pragma unroll
            for (int q = 0; q < 4; q++) acc[mt][nt][q] = 0.f;

    #pragma unroll
    for (int ks = 0; ks < 8; ks++) {
        const int k0 = ks * 16;
        uint32_t a[2][4];
        #pragma unroll
        for (int mt = 0; mt < 2; mt++) {
            const __half* b = aB + mt * 16 * HSTR;
            a[mt][0] = *reinterpret_cast<const uint32_t*>(&b[k0 + 2 * t4]);
            a[mt][1] = *reinterpret_cast<const uint32_t*>(&b[8 * HSTR + k0 + 2 * t4]);
            a[mt][2] = *reinterpret_cast<const uint32_t*>(&b[k0 + 8 + 2 * t4]);
            a[mt][3] = *reinterpret_cast<const uint32_t*>(&b[8 * HSTR + k0 + 8 + 2 * t4]);
        }
        #pragma unroll
        for (int nt = 0; nt < 4; nt++) {
            const __half* bp = bB + nt * 8 * HSTR;
            uint32_t b0 = *reinterpret_cast<const uint32_t*>(&bp[k0 + 2 * t4]);
            uint32_t b1 = *reinterpret_cast<const uint32_t*>(&bp[k0 + 8 + 2 * t4]);
            mma16816(acc[0][nt], a[0], b0, b1);
            mma16816(acc[1][nt], a[1], b0, b1);
        }
    }

    #pragma unroll
    for (int mt = 0; mt < 2; mt++) {
        int r0 = m0 + wm + mt * 16 + g;
        int r1 = r0 + 8;
        #pragma unroll
        for (int nt = 0; nt < 4; nt++) {
            int col = n0 + wn + nt * 8 + 2 * t4;
            if (r0 < M)
                *reinterpret_cast<uint32_t*>(&P[(size_t)r0 * 256 + col]) =
                    h2u(__floats2half2_rn(acc[mt][nt][0], acc[mt][nt][1]));
            if (r1 < M)
                *reinterpret_cast<uint32_t*>(&P[(size_t)r1 * 256 + col]) =
                    h2u(__floats2half2_rn(acc[mt][nt][2], acc[mt][nt][3]));
        }
    }

    // fp16 hidden copy (nb==0 CTA streams it from the smem stage)
    if (nb == 0) {
        #pragma unroll
        for (int i = tid; i < 128 * 16; i += 256) {
            int row = i >> 4, c8 = i & 15;
            int gr = m0 + row;
            if (gr < M)
                *reinterpret_cast<uint4*>(&P[(size_t)gr * 256 + 128 + c8 * 8]) =
                    *reinterpret_cast<const uint4*>(&sA[row * HSTR + c8 * 8]);
        }
    }
}

// ================= gather aggregation: one warp per node, no atomics =================
__global__ __launch_bounds__(256)
void gather_agg(const int4* __restrict__ edges, const float* __restrict__ Wattn,
                const float* __restrict__ rela, int M)
{
    int node = blockIdx.x * 8 + (threadIdx.x >> 5);
    if (node >= M) return;
    int lane = threadIdx.x & 31;
    int c = lane * 4;
    int s = g_off[node], e = g_off[node + 1];
    if (lane == 0) g_deg[node] = (e > s) ? 1 : 0;
    if (e <= s) return;

    float4 wa = *reinterpret_cast<const float4*>(Wattn + c);
    float4 acc = make_float4(0.f, 0.f, 0.f, 0.f);

    for (int i = s; i < e; i++) {
        int eid = g_eidx[i];
        int4 ed = edges[eid];                  // broadcast
        const __half* prow = g_pack + (size_t)ed.y * 256;
        uint2 hs = *reinterpret_cast<const uint2*>(prow + c);
        uint2 hh = *reinterpret_cast<const uint2*>(prow + 128 + c);
        float4 rr = *reinterpret_cast<const float4*>(g_Rr + (size_t)ed.z * DD + c);
        float4 qq = *reinterpret_cast<const float4*>(g_Qq + (size_t)ed.x * DD + c);

        float2 a = __half22float2(*reinterpret_cast<const __half2*>(&hs.x));
        float2 b = __half22float2(*reinterpret_cast<const __half2*>(&hs.y));
        float p = fmaxf(a.x + rr.x + qq.x, 0.f) * wa.x
                + fmaxf(a.y + rr.y + qq.y, 0.f) * wa.y
                + fmaxf(b.x + rr.z + qq.z, 0.f) * wa.z
                + fmaxf(b.y + rr.w + qq.w, 0.f) * wa.w;
        #pragma unroll
        for (int o = 16; o > 0; o >>= 1) p += __shfl_xor_sync(0xffffffffu, p, o);
        float alpha = 1.f / (1.f + __expf(-p));

        float4 mr = *reinterpret_cast<const float4*>(rela + (size_t)ed.z * DD + c);
        float2 ha = __half22float2(*reinterpret_cast<const __half2*>(&hh.x));
        float2 hb = __half22float2(*reinterpret_cast<const __half2*>(&hh.y));
        acc.x += ha.x * mr.x * alpha;
        acc.y += ha.y * mr.y * alpha;
        acc.z += hb.x * mr.z * alpha;
        acc.w += hb.y * mr.w * alpha;
    }
    *reinterpret_cast<float4*>(g_agg + (size_t)node * DD + c) = acc;
}

// ================= GEMM2: out(fp32) = mask*relu(agg @ Wf^T + bf), W fp16 hi/lo x2 =================
#define SM2_BYTES ((128 + 128) * HSTR * 2)  // 69,632 B
__global__ __launch_bounds__(256, 2)
void gemm_h2(const float* __restrict__ A, const __half* __restrict__ Wh,
             const __half* __restrict__ Wl, const float* __restrict__ bias,
             const int* __restrict__ deg, float* __restrict__ C, int M)
{
    extern __shared__ __half smh[];
    __half* sA  = smh;                  // 128 x HSTR
    __half* sWh = smh + 128 * HSTR;     // 64 x HSTR
    __half* sWl = smh + 192 * HSTR;     // 64 x HSTR

    const int tid = threadIdx.x;
    const int mb = blockIdx.x >> 1;
    const int nb = blockIdx.x & 1;
    const int m0 = mb * 128;
    const int n0 = nb * 64;

    const float4* A4 = reinterpret_cast<const float4*>(A);
    #pragma unroll
    for (int i = tid; i < 128 * 32; i += 256) {
        int row = i >> 5, c4 = i & 31;
        int gr = m0 + row;
        float4 v = make_float4(0.f, 0.f, 0.f, 0.f);
        if (gr < M) v = A4[(size_t)gr * 32 + c4];
        uint2 u = make_uint2(h2u(__floats2half2_rn(v.x, v.y)),
                             h2u(__floats2half2_rn(v.z, v.w)));
        *reinterpret_cast<uint2*>(&sA[row * HSTR + c4 * 4]) = u;
    }
    const uint4* WH4 = reinterpret_cast<const uint4*>(Wh);
    const uint4* WL4 = reinterpret_cast<const uint4*>(Wl);
    #pragma unroll
    for (int i = tid; i < 64 * 16; i += 256) {
        int row = i >> 4, c8 = i & 15;
        *reinterpret_cast<uint4*>(&sWh[row * HSTR + c8 * 8]) = WH4[(size_t)(n0 + row) * 16 + c8];
        *reinterpret_cast<uint4*>(&sWl[row * HSTR + c8 * 8]) = WL4[(size_t)(n0 + row) * 16 + c8];
    }
    __syncthreads();

    const int lane = tid & 31;
    const int wid = tid >> 5;
    const int g = lane >> 2;
    const int t4 = lane & 3;
    const int wm = (wid >> 1) * 32;
    const int wn = (wid & 1) * 32;

    const __half* aB  = sA  + (wm + g) * HSTR;
    const __half* bhB = sWh + (wn + g) * HSTR;
    const __half* blB = sWl + (wn + g) * HSTR;

    float acc[2][4][4];
    #pragma unroll
    for (int mt = 0; mt < 2; mt++)
        #pragma unroll
        for (int nt = 0; nt < 4; nt++)
            #pragma unroll
            for (int q = 0; q < 4; q++) acc[mt][nt][q] = 0.f;

    #pragma unroll
    for (int ks = 0; ks < 8; ks++) {
        const int k0 = ks * 16;
        uint32_t a[2][4];
        #pragma unroll
        for (int mt = 0; mt < 2; mt++) {
            const __half* b = aB + mt * 16 * HSTR;
            a[mt][0] = *reinterpret_cast<const uint32_t*>(&b[k0 + 2 * t4]);
            a[mt][1] = *reinterpret_cast<const uint32_t*>(&b[8 * HSTR + k0 + 2 * t4]);
            a[mt][2] = *reinterpret_cast<const uint32_t*>(&b[k0 + 8 + 2 * t4]);
            a[mt][3] = *reinterpret_cast<const uint32_t*>(&b[8 * HSTR + k0 + 8 + 2 * t4]);
        }
        #pragma unroll
        for (int nt = 0; nt < 4; nt++) {
            const __half* bh = bhB + nt * 8 * HSTR;
            const __half* bl = blB + nt * 8 * HSTR;
            uint32_t bh0 = *reinterpret_cast<const uint32_t*>(&bh[k0 + 2 * t4]);
            uint32_t bh1 = *reinterpret_cast<const uint32_t*>(&bh[k0 + 8 + 2 * t4]);
            uint32_t bl0 = *reinterpret_cast<const uint32_t*>(&bl[k0 + 2 * t4]);
            uint32_t bl1 = *reinterpret_cast<const uint32_t*>(&bl[k0 + 8 + 2 * t4]);
            #pragma unroll
            for (int mt = 0; mt < 2; mt++) {
                mma16816(acc[mt][nt], a[mt], bh0, bh1);
                mma16816(acc[mt][nt], a[mt], bl0, bl1);
            }
        }
    }

    #pragma unroll
    for (int mt = 0; mt < 2; mt++) {
        int r0 = m0 + wm + mt * 16 + g;
        int r1 = r0 + 8;
        bool k0ok = r0 < M, k1ok = r1 < M;
        bool keep0 = k0ok && deg[r0] > 0;
        bool keep1 = k1ok && deg[r1] > 0;
        #pragma unroll
        for (int nt = 0; nt < 4; nt++) {
            int col = n0 + wn + nt * 8 + 2 * t4;
            float b0 = bias[col], b1 = bias[col + 1];
            float c0 = keep0 ? fmaxf(acc[mt][nt][0] + b0, 0.f) : 0.f;
            float c1 = keep0 ? fmaxf(acc[mt][nt][1] + b1, 0.f) : 0.f;
            float c2 = keep1 ? fmaxf(acc[mt][nt][2] + b0, 0.f) : 0.f;
            float c3 = keep1 ? fmaxf(acc[mt][nt][3] + b1, 0.f) : 0.f;
            if (k0ok) *reinterpret_cast<float2*>(C + (size_t)r0 * DD + col) = make_float2(c0, c1);
            if (k1ok) *reinterpret_cast<float2*>(C + (size_t)r1 * DD + col) = make_float2(c2, c3);
        }
    }
}

// -------- launch --------
extern "C" void kernel_launch(void* const* d_in, const int* in_sizes, int n_in,
                              void* d_out, int out_size)
{
    const float* query  = (const float*)d_in[0];
    const float* hidden = (const float*)d_in[3];
    const int*   edges  = (const int*)d_in[4];
    const float* Ws     = (const float*)d_in[6];
    const float* Wr     = (const float*)d_in[7];
    const float* Wqr    = (const float*)d_in[8];
    const float* Wqr_b  = (const float*)d_in[9];
    const float* Wattn  = (const float*)d_in[10];
    const float* rela   = (const float*)d_in[11];
    const float* mlp1_w = (const float*)d_in[12];
    const float* mlp1_b = (const float*)d_in[13];
    const float* mlp2_w = (const float*)d_in[14];
    const float* mlp2_b = (const float*)d_in[15];

    int M = in_sizes[3] / DD;     // B*N = 200000
    int E = in_sizes[4] / 4;      // 600000
    int R = in_sizes[11] / DD;    // 200
    int B = in_sizes[0] / DD;     // 4

    void *aggp = 0, *packp = 0, *bfp = 0, *wshp = 0, *wfhp = 0, *wflp = 0, *cntp = 0, *degp = 0;
    cudaGetSymbolAddress(&aggp,  g_agg);
    cudaGetSymbolAddress(&packp, g_pack);
    cudaGetSymbolAddress(&bfp,   g_bf);
    cudaGetSymbolAddress(&wshp,  g_WsH);
    cudaGetSymbolAddress(&wfhp,  g_WfH);
    cudaGetSymbolAddress(&wflp,  g_WfL);
    cudaGetSymbolAddress(&cntp,  g_cnt);
    cudaGetSymbolAddress(&degp,  g_deg);

    // only the edge-count histogram needs zeroing each launch
    cudaMemsetAsync(cntp, 0, (size_t)M * sizeof(int), 0);

    prep_kernel<<<DD + R + B, DD>>>(mlp1_w, mlp1_b, mlp2_w, mlp2_b,
                                    rela, Wr, query, Wqr, Wqr_b, R);
    convert_kernel<<<(DD * DD + 255) / 256, 256>>>(Ws);

    // CSR build
    int nb = (M + 1023) / 1024;
    hist_k<<<(E + 255) / 256, 256>>>((const int4*)edges, E);
    scan1_k<<<nb, 256>>>(M);
    scan2_k<<<1, 256>>>(nb, E, M);
    scan3_k<<<(M + 255) / 256, 256>>>(M);
    scatter_k<<<(E + 255) / 256, 256>>>((const int4*)edges, E);

    cudaFuncSetAttribute(gemm_h1, cudaFuncAttributeMaxDynamicSharedMemorySize, SM1_BYTES);
    cudaFuncSetAttribute(gemm_h2, cudaFuncAttributeMaxDynamicSharedMemorySize, SM2_BYTES);
    int grid = ((M + 127) / 128) * 2;

    // pack = [fp16(hidden @ Ws^T) | fp16(hidden)]
    gemm_h1<<<grid, 256, SM1_BYTES>>>(hidden, (const __half*)wshp, (__half*)packp, M);
    // per-node gather aggregation (no atomics)
    gather_agg<<<(M + 7) / 8, 256>>>((const int4*)edges, Wattn, rela, M);
    // out = mask(deg) * relu(agg @ Wf^T + bf)
    gemm_h2<<<grid, 256, SM2_BYTES>>>((const float*)aggp, (const __half*)wfhp,
                                      (const __half*)wflp, (const float*)bfp,
                                      (const int*)degp, (float*)d_out, M);
}

// round 14
// speedup vs baseline: 1.0495x; 1.0495x over previous
#include <cuda_runtime.h>
#include <cuda_fp16.h>
#include <cstdint>

#define DD 128
#define HSTR 136                 // smem half-row stride (136 halves = 272B ≡ 4 banks)
#define MAXM 200000
#define MAXR 256
#define MAXB 8

// -------- scratch (static device memory; no allocs allowed) --------
__device__ __half g_pack[(size_t)MAXM * 256]; // per row: [0:128)=Hs fp16, [128:256)=hidden fp16
__device__ float  g_agg[(size_t)MAXM * DD];   // segment_sum output (102.4 MB)
__device__ int    g_deg[MAXM];                // receive flags
__device__ float  g_Rr[MAXR * DD];            // rela_embed @ Wr^T
__device__ float  g_Qq[MAXB * DD];            // query @ Wqr^T + b
__device__ float  g_Wf[DD * DD];              // mlp2 @ mlp1, natural [n][k]
__device__ float  g_bf[DD];                   // mlp2 @ b1 + b2
__device__ __half g_WsH[DD * DD];             // fp16(Ws_attn_w) [n][k]
__device__ __half g_WfH[DD * DD];             // fp16 hi part of Wf [n][k]
__device__ __half g_WfL[DD * DD];             // fp16 lo part of Wf [n][k]

__device__ __forceinline__ uint32_t h2u(__half2 h) {
    return *reinterpret_cast<uint32_t*>(&h);
}

// m16n8k16 f16 MMA, f32 accum (baseline PTX sm_80+)
__device__ __forceinline__ void mma16816(float* d, const uint32_t* a, uint32_t b0, uint32_t b1) {
    asm volatile(
        "mma.sync.aligned.m16n8k16.row.col.f32.f16.f16.f32 "
        "{%0,%1,%2,%3}, {%4,%5,%6,%7}, {%8,%9}, {%0,%1,%2,%3};"
        : "+f"(d[0]), "+f"(d[1]), "+f"(d[2]), "+f"(d[3])
        : "r"(a[0]), "r"(a[1]), "r"(a[2]), "r"(a[3]), "r"(b0), "r"(b1));
}

// ================= prep: Wf (natural [n][k]), bf, Rr, Qq =================
__global__ void prep_kernel(const float* __restrict__ mlp1_w, const float* __restrict__ mlp1_b,
                            const float* __restrict__ mlp2_w, const float* __restrict__ mlp2_b,
                            const float* __restrict__ rela,   const float* __restrict__ Wr,
                            const float* __restrict__ query,  const float* __restrict__ Wqr,
                            const float* __restrict__ Wqr_b,  int R)
{
    int t = threadIdx.x;
    int bx = blockIdx.x;
    if (bx < DD) {
        int i = bx;
        float acc = 0.f;
        for (int j = 0; j < DD; j++) acc += mlp2_w[i * DD + j] * mlp1_w[j * DD + t];
        g_Wf[i * DD + t] = acc;
        __shared__ float s[DD];
        s[t] = mlp2_w[i * DD + t] * mlp1_b[t];
        __syncthreads();
        if (t == 0) {
            float b = 0.f;
            for (int j = 0; j < DD; j++) b += s[j];
            g_bf[i] = b + mlp2_b[i];
        }
    } else if (bx < DD + R) {
        int r = bx - DD;
        float acc = 0.f;
        for (int d = 0; d < DD; d++) acc += rela[r * DD + d] * Wr[t * DD + d];
        g_Rr[r * DD + t] = acc;
    } else {
        int b = bx - DD - R;
        float acc = Wqr_b[t];
        for (int d = 0; d < DD; d++) acc += query[b * DD + d] * Wqr[t * DD + d];
        g_Qq[b * DD + t] = acc;
    }
}

// convert Ws -> fp16; Wf -> fp16 hi/lo split
__global__ void convert_kernel(const float* __restrict__ Ws) {
    int i = blockIdx.x * 256 + threadIdx.x;
    if (i >= DD * DD) return;
    g_WsH[i] = __float2half_rn(Ws[i]);
    float w = g_Wf[i];
    __half h = __float2half_rn(w);
    g_WfH[i] = h;
    g_WfL[i] = __float2half_rn(w - __half2float(h));
}

// ================= GEMM1: pack = [fp16(hidden @ Ws^T) | fp16(hidden)] =================
#define SM1_BYTES ((128 + 64) * HSTR * 2)   // 52,224 B
__global__ __launch_bounds__(256, 2)
void gemm_h1(const float* __restrict__ A, const __half* __restrict__ W,
             __half* __restrict__ P, int M)
{
    extern __shared__ __half smh[];
    __half* sA = smh;                  // 128 x HSTR
    __half* sW = smh + 128 * HSTR;     // 64 x HSTR

    const int tid = threadIdx.x;
    const int mb = blockIdx.x >> 1;
    const int nb = blockIdx.x & 1;
    const int m0 = mb * 128;
    const int n0 = nb * 64;

    const float4* A4 = reinterpret_cast<const float4*>(A);
    #pragma unroll
    for (int i = tid; i < 128 * 32; i += 256) {
        int row = i >> 5, c4 = i & 31;
        int gr = m0 + row;
        float4 v = make_float4(0.f, 0.f, 0.f, 0.f);
        if (gr < M) v = A4[(size_t)gr * 32 + c4];
        uint2 u = make_uint2(h2u(__floats2half2_rn(v.x, v.y)),
                             h2u(__floats2half2_rn(v.z, v.w)));
        *reinterpret_cast<uint2*>(&sA[row * HSTR + c4 * 4]) = u;
    }
    const uint4* W4 = reinterpret_cast<const uint4*>(W);
    #pragma unroll
    for (int i = tid; i < 64 * 16; i += 256) {
        int row = i >> 4, c8 = i & 15;
        *reinterpret_cast<uint4*>(&sW[row * HSTR + c8 * 8]) = W4[(size_t)(n0 + row) * 16 + c8];
    }
    __syncthreads();

    const int lane = tid & 31;
    const int wid = tid >> 5;
    const int g = lane >> 2;
    const int t4 = lane & 3;
    const int wm = (wid >> 1) * 32;
    const int wn = (wid & 1) * 32;

    const __half* aB = sA + (wm + g) * HSTR;
    const __half* bB = sW + (wn + g) * HSTR;

    float acc[2][4][4];
    #pragma unroll
    for (int mt = 0; mt < 2; mt++)
        #pragma unroll
        for (int nt = 0; nt < 4; nt++)
            #pragma unroll
            for (int q = 0; q < 4; q++) acc[mt][nt][q] = 0.f;

    #pragma unroll
    for (int ks = 0; ks < 8; ks++) {
        const int k0 = ks * 16;
        uint32_t a[2][4];
        #pragma unroll
        for (int mt = 0; mt < 2; mt++) {
            const __half* b = aB + mt * 16 * HSTR;
            a[mt][0] = *reinterpret_cast<const uint32_t*>(&b[k0 + 2 * t4]);
            a[mt][1] = *reinterpret_cast<const uint32_t*>(&b[8 * HSTR + k0 + 2 * t4]);
            a[mt][2] = *reinterpret_cast<const uint32_t*>(&b[k0 + 8 + 2 * t4]);
            a[mt][3] = *reinterpret_cast<const uint32_t*>(&b[8 * HSTR + k0 + 8 + 2 * t4]);
        }
        #pragma unroll
        for (int nt = 0; nt < 4; nt++) {
            const __half* bp = bB + nt * 8 * HSTR;
            uint32_t b0 = *reinterpret_cast<const uint32_t*>(&bp[k0 + 2 * t4]);
            uint32_t b1 = *reinterpret_cast<const uint32_t*>(&bp[k0 + 8 + 2 * t4]);
            mma16816(acc[0][nt], a[0], b0, b1);
            mma16816(acc[1][nt], a[1], b0, b1);
        }
    }

    #pragma unroll
    for (int mt = 0; mt < 2; mt++) {
        int r0 = m0 + wm + mt * 16 + g;
        int r1 = r0 + 8;
        #pragma unroll
        for (int nt = 0; nt < 4; nt++) {
            int col = n0 + wn + nt * 8 + 2 * t4;
            if (r0 < M)
                *reinterpret_cast<uint32_t*>(&P[(size_t)r0 * 256 + col]) =
                    h2u(__floats2half2_rn(acc[mt][nt][0], acc[mt][nt][1]));
            if (r1 < M)
                *reinterpret_cast<uint32_t*>(&P[(size_t)r1 * 256 + col]) =
                    h2u(__floats2half2_rn(acc[mt][nt][2], acc[mt][nt][3]));
        }
    }

    // fp16 hidden copy (nb==0 CTA streams it from the smem stage)
    if (nb == 0) {
        #pragma unroll
        for (int i = tid; i < 128 * 16; i += 256) {
            int row = i >> 4, c8 = i & 15;
            int gr = m0 + row;
            if (gr < M)
                *reinterpret_cast<uint4*>(&P[(size_t)gr * 256 + 128 + c8 * 8]) =
                    *reinterpret_cast<const uint4*>(&sA[row * HSTR + c8 * 8]);
        }
    }
}

// ================= GEMM2: out(fp32) = mask*relu(agg @ Wf^T + bf), W fp16 hi/lo x2 =================
#define SM2_BYTES ((128 + 128) * HSTR * 2)  // 69,632 B
__global__ __launch_bounds__(256, 2)
void gemm_h2(const float* __restrict__ A, const __half* __restrict__ Wh,
             const __half* __restrict__ Wl, const float* __restrict__ bias,
             const int* __restrict__ deg, float* __restrict__ C, int M)
{
    extern __shared__ __half smh[];
    __half* sA  = smh;                  // 128 x HSTR
    __half* sWh = smh + 128 * HSTR;     // 64 x HSTR
    __half* sWl = smh + 192 * HSTR;     // 64 x HSTR

    const int tid = threadIdx.x;
    const int mb = blockIdx.x >> 1;
    const int nb = blockIdx.x & 1;
    const int m0 = mb * 128;
    const int n0 = nb * 64;

    const float4* A4 = reinterpret_cast<const float4*>(A);
    #pragma unroll
    for (int i = tid; i < 128 * 32; i += 256) {
        int row = i >> 5, c4 = i & 31;
        int gr = m0 + row;
        float4 v = make_float4(0.f, 0.f, 0.f, 0.f);
        if (gr < M) v = A4[(size_t)gr * 32 + c4];
        uint2 u = make_uint2(h2u(__floats2half2_rn(v.x, v.y)),
                             h2u(__floats2half2_rn(v.z, v.w)));
        *reinterpret_cast<uint2*>(&sA[row * HSTR + c4 * 4]) = u;
    }
    const uint4* WH4 = reinterpret_cast<const uint4*>(Wh);
    const uint4* WL4 = reinterpret_cast<const uint4*>(Wl);
    #pragma unroll
    for (int i = tid; i < 64 * 16; i += 256) {
        int row = i >> 4, c8 = i & 15;
        *reinterpret_cast<uint4*>(&sWh[row * HSTR + c8 * 8]) = WH4[(size_t)(n0 + row) * 16 + c8];
        *reinterpret_cast<uint4*>(&sWl[row * HSTR + c8 * 8]) = WL4[(size_t)(n0 + row) * 16 + c8];
    }
    __syncthreads();

    const int lane = tid & 31;
    const int wid = tid >> 5;
    const int g = lane >> 2;
    const int t4 = lane & 3;
    const int wm = (wid >> 1) * 32;
    const int wn = (wid & 1) * 32;

    const __half* aB  = sA  + (wm + g) * HSTR;
    const __half* bhB = sWh + (wn + g) * HSTR;
    const __half* blB = sWl + (wn + g) * HSTR;

    float acc[2][4][4];
    #pragma unroll
    for (int mt = 0; mt < 2; mt++)
        #pragma unroll
        for (int nt = 0; nt < 4; nt++)
            #pragma unroll
            for (int q = 0; q < 4; q++) acc[mt][nt][q] = 0.f;

    #pragma unroll
    for (int ks = 0; ks < 8; ks++) {
        const int k0 = ks * 16;
        uint32_t a[2][4];
        #pragma unroll
        for (int mt = 0; mt < 2; mt++) {
            const __half* b = aB + mt * 16 * HSTR;
            a[mt][0] = *reinterpret_cast<const uint32_t*>(&b[k0 + 2 * t4]);
            a[mt][1] = *reinterpret_cast<const uint32_t*>(&b[8 * HSTR + k0 + 2 * t4]);
            a[mt][2] = *reinterpret_cast<const uint32_t*>(&b[k0 + 8 + 2 * t4]);
            a[mt][3] = *reinterpret_cast<const uint32_t*>(&b[8 * HSTR + k0 + 8 + 2 * t4]);
        }
        #pragma unroll
        for (int nt = 0; nt < 4; nt++) {
            const __half* bh = bhB + nt * 8 * HSTR;
            const __half* bl = blB + nt * 8 * HSTR;
            uint32_t bh0 = *reinterpret_cast<const uint32_t*>(&bh[k0 + 2 * t4]);
            uint32_t bh1 = *reinterpret_cast<const uint32_t*>(&bh[k0 + 8 + 2 * t4]);
            uint32_t bl0 = *reinterpret_cast<const uint32_t*>(&bl[k0 + 2 * t4]);
            uint32_t bl1 = *reinterpret_cast<const uint32_t*>(&bl[k0 + 8 + 2 * t4]);
            #pragma unroll
            for (int mt = 0; mt < 2; mt++) {
                mma16816(acc[mt][nt], a[mt], bh0, bh1);
                mma16816(acc[mt][nt], a[mt], bl0, bl1);
            }
        }
    }

    #pragma unroll
    for (int mt = 0; mt < 2; mt++) {
        int r0 = m0 + wm + mt * 16 + g;
        int r1 = r0 + 8;
        bool k0ok = r0 < M, k1ok = r1 < M;
        bool keep0 = k0ok && deg[r0] > 0;
        bool keep1 = k1ok && deg[r1] > 0;
        #pragma unroll
        for (int nt = 0; nt < 4; nt++) {
            int col = n0 + wn + nt * 8 + 2 * t4;
            float b0 = bias[col], b1 = bias[col + 1];
            float c0 = keep0 ? fmaxf(acc[mt][nt][0] + b0, 0.f) : 0.f;
            float c1 = keep0 ? fmaxf(acc[mt][nt][1] + b1, 0.f) : 0.f;
            float c2 = keep1 ? fmaxf(acc[mt][nt][2] + b0, 0.f) : 0.f;
            float c3 = keep1 ? fmaxf(acc[mt][nt][3] + b1, 0.f) : 0.f;
            if (k0ok) *reinterpret_cast<float2*>(C + (size_t)r0 * DD + col) = make_float2(c0, c1);
            if (k1ok) *reinterpret_cast<float2*>(C + (size_t)r1 * DD + col) = make_float2(c2, c3);
        }
    }
}

// -------- edge kernel: TWO edges per warp (R11 shape) + packed row gathers (R12 traffic) --------
__global__ __launch_bounds__(256)
void edge_kernel(const int4* __restrict__ edges, const float* __restrict__ Wattn,
                 const float* __restrict__ rela, int E)
{
    const int base = blockIdx.x * 16 + ((threadIdx.x >> 5) << 1);
    const int lane = threadIdx.x & 31;
    const int c = lane * 4;
    const bool v0 = base < E;
    const bool v1 = base + 1 < E;
    const int4 ed0 = v0 ? edges[base]     : make_int4(0, 0, 0, 0);
    const int4 ed1 = v1 ? edges[base + 1] : make_int4(0, 0, 0, 0);

    // all gathers up front: packed rows (Hs fp16 | hidden fp16), Rr, Qq (L2-resident)
    const __half* p0 = g_pack + (size_t)ed0.y * 256;
    const __half* p1 = g_pack + (size_t)ed1.y * 256;
    uint2 hs0 = *reinterpret_cast<const uint2*>(p0 + c);
    uint2 hs1 = *reinterpret_cast<const uint2*>(p1 + c);
    uint2 hh0 = *reinterpret_cast<const uint2*>(p0 + 128 + c);
    uint2 hh1 = *reinterpret_cast<const uint2*>(p1 + 128 + c);
    float4 rr0 = *reinterpret_cast<const float4*>(g_Rr + (size_t)ed0.z * DD + c);
    float4 rr1 = *reinterpret_cast<const float4*>(g_Rr + (size_t)ed1.z * DD + c);
    float4 mr0 = *reinterpret_cast<const float4*>(rela + (size_t)ed0.z * DD + c);
    float4 mr1 = *reinterpret_cast<const float4*>(rela + (size_t)ed1.z * DD + c);
    float4 qq0 = *reinterpret_cast<const float4*>(g_Qq + (size_t)ed0.x * DD + c);
    float4 qq1 = *reinterpret_cast<const float4*>(g_Qq + (size_t)ed1.x * DD + c);
    float4 wa  = *reinterpret_cast<const float4*>(Wattn + c);

    float2 a0 = __half22float2(*reinterpret_cast<const __half2*>(&hs0.x));
    float2 b0 = __half22float2(*reinterpret_cast<const __half2*>(&hs0.y));
    float2 a1 = __half22float2(*reinterpret_cast<const __half2*>(&hs1.x));
    float2 b1 = __half22float2(*reinterpret_cast<const __half2*>(&hs1.y));

    float pp0 = fmaxf(a0.x + rr0.x + qq0.x, 0.f) * wa.x
              + fmaxf(a0.y + rr0.y + qq0.y, 0.f) * wa.y
              + fmaxf(b0.x + rr0.z + qq0.z, 0.f) * wa.z
              + fmaxf(b0.y + rr0.w + qq0.w, 0.f) * wa.w;
    float pp1 = fmaxf(a1.x + rr1.x + qq1.x, 0.f) * wa.x
              + fmaxf(a1.y + rr1.y + qq1.y, 0.f) * wa.y
              + fmaxf(b1.x + rr1.z + qq1.z, 0.f) * wa.z
              + fmaxf(b1.y + rr1.w + qq1.w, 0.f) * wa.w;
    #pragma unroll
    for (int o = 16; o > 0; o >>= 1) {
        pp0 += __shfl_xor_sync(0xffffffffu, pp0, o);
        pp1 += __shfl_xor_sync(0xffffffffu, pp1, o);
    }
    float alpha0 = 1.f / (1.f + __expf(-pp0));
    float alpha1 = 1.f / (1.f + __expf(-pp1));

    if (v0) {
        float2 ha = __half22float2(*reinterpret_cast<const __half2*>(&hh0.x));
        float2 hb = __half22float2(*reinterpret_cast<const __half2*>(&hh0.y));
        float* dst = g_agg + (size_t)ed0.w * DD + c;
        asm volatile("red.global.add.v4.f32 [%0], {%1,%2,%3,%4};"
                     :: "l"(dst),
                        "f"(ha.x * mr0.x * alpha0), "f"(ha.y * mr0.y * alpha0),
                        "f"(hb.x * mr0.z * alpha0), "f"(hb.y * mr0.w * alpha0) : "memory");
        if (lane == 0) g_deg[ed0.w] = 1;
    }
    if (v1) {
        float2 ha = __half22float2(*reinterpret_cast<const __half2*>(&hh1.x));
        float2 hb = __half22float2(*reinterpret_cast<const __half2*>(&hh1.y));
        float* dst = g_agg + (size_t)ed1.w * DD + c;
        asm volatile("red.global.add.v4.f32 [%0], {%1,%2,%3,%4};"
                     :: "l"(dst),
                        "f"(ha.x * mr1.x * alpha1), "f"(ha.y * mr1.y * alpha1),
                        "f"(hb.x * mr1.z * alpha1), "f"(hb.y * mr1.w * alpha1) : "memory");
        if (lane == 0) g_deg[ed1.w] = 1;
    }
}

// -------- launch --------
extern "C" void kernel_launch(void* const* d_in, const int* in_sizes, int n_in,
                              void* d_out, int out_size)
{
    const float* query  = (const float*)d_in[0];
    const float* hidden = (const float*)d_in[3];
    const int*   edges  = (const int*)d_in[4];
    const float* Ws     = (const float*)d_in[6];
    const float* Wr     = (const float*)d_in[7];
    const float* Wqr    = (const float*)d_in[8];
    const float* Wqr_b  = (const float*)d_in[9];
    const float* Wattn  = (const float*)d_in[10];
    const float* rela   = (const float*)d_in[11];
    const float* mlp1_w = (const float*)d_in[12];
    const float* mlp1_b = (const float*)d_in[13];
    const float* mlp2_w = (const float*)d_in[14];
    const float* mlp2_b = (const float*)d_in[15];

    int M = in_sizes[3] / DD;     // B*N = 200000
    int E = in_sizes[4] / 4;      // 600000
    int R = in_sizes[11] / DD;    // 200
    int B = in_sizes[0] / DD;     // 4

    void *aggp = 0, *degp = 0, *packp = 0, *bfp = 0, *wshp = 0, *wfhp = 0, *wflp = 0;
    cudaGetSymbolAddress(&aggp,  g_agg);
    cudaGetSymbolAddress(&degp,  g_deg);
    cudaGetSymbolAddress(&packp, g_pack);
    cudaGetSymbolAddress(&bfp,   g_bf);
    cudaGetSymbolAddress(&wshp,  g_WsH);
    cudaGetSymbolAddress(&wfhp,  g_WfH);
    cudaGetSymbolAddress(&wflp,  g_WfL);

    cudaMemsetAsync(aggp, 0, (size_t)M * DD * sizeof(float), 0);
    cudaMemsetAsync(degp, 0, (size_t)M * sizeof(int), 0);

    prep_kernel<<<DD + R + B, DD>>>(mlp1_w, mlp1_b, mlp2_w, mlp2_b,
                                    rela, Wr, query, Wqr, Wqr_b, R);
    convert_kernel<<<(DD * DD + 255) / 256, 256>>>(Ws);

    cudaFuncSetAttribute(gemm_h1, cudaFuncAttributeMaxDynamicSharedMemorySize, SM1_BYTES);
    cudaFuncSetAttribute(gemm_h2, cudaFuncAttributeMaxDynamicSharedMemorySize, SM2_BYTES);
    int grid = ((M + 127) / 128) * 2;

    // pack = [fp16(hidden @ Ws^T) | fp16(hidden)]
    gemm_h1<<<grid, 256, SM1_BYTES>>>(hidden, (const __half*)wshp, (__half*)packp, M);
    // per-edge attention + scatter (2 edges per warp)
    edge_kernel<<<(E + 15) / 16, 256>>>((const int4*)edges, Wattn, rela, E);
    // out = mask(deg) * relu(agg @ Wf^T + bf)
    gemm_h2<<<grid, 256, SM2_BYTES>>>((const float*)aggp, (const __half*)wfhp,
                                      (const __half*)wflp, (const float*)bfp,
                                      (const int*)degp, (float*)d_out, M);
}

// round 15
// speedup vs baseline: 1.0557x; 1.0059x over previous
#include <cuda_runtime.h>
#include <cuda_fp16.h>
#include <cstdint>

#define DD 128
#define HSTR 136                 // smem half-row stride (136 halves = 272B ≡ 4 banks)
#define MAXM 200000
#define MAXR 256
#define MAXB 8

// -------- scratch (static device memory; no allocs allowed) --------
__device__ __half g_pack[(size_t)MAXM * 256]; // per row: [0:128)=Hs fp16, [128:256)=hidden fp16
__device__ float  g_agg[(size_t)MAXM * DD];   // segment_sum output (102.4 MB)
__device__ int    g_deg[MAXM];                // receive flags
__device__ float  g_Rr[MAXR * DD];            // rela_embed @ Wr^T
__device__ float  g_Qq[MAXB * DD];            // query @ Wqr^T + b
__device__ float  g_Wf[DD * DD];              // mlp2 @ mlp1, natural [n][k]
__device__ float  g_bf[DD];                   // mlp2 @ b1 + b2
__device__ __half g_WsH[DD * DD];             // fp16(Ws_attn_w) [n][k]
__device__ __half g_WfH[DD * DD];             // fp16 hi part of Wf [n][k]
__device__ __half g_WfL[DD * DD];             // fp16 lo part of Wf [n][k]

__device__ __forceinline__ uint32_t h2u(__half2 h) {
    return *reinterpret_cast<uint32_t*>(&h);
}

// m16n8k16 f16 MMA, f32 accum (baseline PTX sm_80+)
__device__ __forceinline__ void mma16816(float* d, const uint32_t* a, uint32_t b0, uint32_t b1) {
    asm volatile(
        "mma.sync.aligned.m16n8k16.row.col.f32.f16.f16.f32 "
        "{%0,%1,%2,%3}, {%4,%5,%6,%7}, {%8,%9}, {%0,%1,%2,%3};"
        : "+f"(d[0]), "+f"(d[1]), "+f"(d[2]), "+f"(d[3])
        : "r"(a[0]), "r"(a[1]), "r"(a[2]), "r"(a[3]), "r"(b0), "r"(b1));
}

// ================= prep: Wf (natural [n][k]), bf, Rr, Qq =================
__global__ void prep_kernel(const float* __restrict__ mlp1_w, const float* __restrict__ mlp1_b,
                            const float* __restrict__ mlp2_w, const float* __restrict__ mlp2_b,
                            const float* __restrict__ rela,   const float* __restrict__ Wr,
                            const float* __restrict__ query,  const float* __restrict__ Wqr,
                            const float* __restrict__ Wqr_b,  int R)
{
    int t = threadIdx.x;
    int bx = blockIdx.x;
    if (bx < DD) {
        int i = bx;
        float acc = 0.f;
        for (int j = 0; j < DD; j++) acc += mlp2_w[i * DD + j] * mlp1_w[j * DD + t];
        g_Wf[i * DD + t] = acc;
        __shared__ float s[DD];
        s[t] = mlp2_w[i * DD + t] * mlp1_b[t];
        __syncthreads();
        if (t == 0) {
            float b = 0.f;
            for (int j = 0; j < DD; j++) b += s[j];
            g_bf[i] = b + mlp2_b[i];
        }
    } else if (bx < DD + R) {
        int r = bx - DD;
        float acc = 0.f;
        for (int d = 0; d < DD; d++) acc += rela[r * DD + d] * Wr[t * DD + d];
        g_Rr[r * DD + t] = acc;
    } else {
        int b = bx - DD - R;
        float acc = Wqr_b[t];
        for (int d = 0; d < DD; d++) acc += query[b * DD + d] * Wqr[t * DD + d];
        g_Qq[b * DD + t] = acc;
    }
}

// convert Ws -> fp16; Wf -> fp16 hi/lo split
__global__ void convert_kernel(const float* __restrict__ Ws) {
    int i = blockIdx.x * 256 + threadIdx.x;
    if (i >= DD * DD) return;
    g_WsH[i] = __float2half_rn(Ws[i]);
    float w = g_Wf[i];
    __half h = __float2half_rn(w);
    g_WfH[i] = h;
    g_WfL[i] = __float2half_rn(w - __half2float(h));
}

// ================= GEMM1: pack = [fp16(hidden @ Ws^T) | fp16(hidden)] =================
#define SM1_BYTES ((128 + 64) * HSTR * 2)   // 52,224 B
__global__ __launch_bounds__(256, 2)
void gemm_h1(const float* __restrict__ A, const __half* __restrict__ W,
             __half* __restrict__ P, int M)
{
    extern __shared__ __half smh[];
    __half* sA = smh;                  // 128 x HSTR
    __half* sW = smh + 128 * HSTR;     // 64 x HSTR

    const int tid = threadIdx.x;
    const int mb = blockIdx.x >> 1;
    const int nb = blockIdx.x & 1;
    const int m0 = mb * 128;
    const int n0 = nb * 64;

    const float4* A4 = reinterpret_cast<const float4*>(A);
    #pragma unroll
    for (int i = tid; i < 128 * 32; i += 256) {
        int row = i >> 5, c4 = i & 31;
        int gr = m0 + row;
        float4 v = make_float4(0.f, 0.f, 0.f, 0.f);
        if (gr < M) v = A4[(size_t)gr * 32 + c4];
        uint2 u = make_uint2(h2u(__floats2half2_rn(v.x, v.y)),
                             h2u(__floats2half2_rn(v.z, v.w)));
        *reinterpret_cast<uint2*>(&sA[row * HSTR + c4 * 4]) = u;
    }
    const uint4* W4 = reinterpret_cast<const uint4*>(W);
    #pragma unroll
    for (int i = tid; i < 64 * 16; i += 256) {
        int row = i >> 4, c8 = i & 15;
        *reinterpret_cast<uint4*>(&sW[row * HSTR + c8 * 8]) = W4[(size_t)(n0 + row) * 16 + c8];
    }
    __syncthreads();

    const int lane = tid & 31;
    const int wid = tid >> 5;
    const int g = lane >> 2;
    const int t4 = lane & 3;
    const int wm = (wid >> 1) * 32;
    const int wn = (wid & 1) * 32;

    const __half* aB = sA + (wm + g) * HSTR;
    const __half* bB = sW + (wn + g) * HSTR;

    float acc[2][4][4];
    #pragma unroll
    for (int mt = 0; mt < 2; mt++)
        #pragma unroll
        for (int nt = 0; nt < 4; nt++)
            #pragma unroll
            for (int q = 0; q < 4; q++) acc[mt][nt][q] = 0.f;

    #pragma unroll
    for (int ks = 0; ks < 8; ks++) {
        const int k0 = ks * 16;
        uint32_t a[2][4];
        #pragma unroll
        for (int mt = 0; mt < 2; mt++) {
            const __half* b = aB + mt * 16 * HSTR;
            a[mt][0] = *reinterpret_cast<const uint32_t*>(&b[k0 + 2 * t4]);
            a[mt][1] = *reinterpret_cast<const uint32_t*>(&b[8 * HSTR + k0 + 2 * t4]);
            a[mt][2] = *reinterpret_cast<const uint32_t*>(&b[k0 + 8 + 2 * t4]);
            a[mt][3] = *reinterpret_cast<const uint32_t*>(&b[8 * HSTR + k0 + 8 + 2 * t4]);
        }
        #pragma unroll
        for (int nt = 0; nt < 4; nt++) {
            const __half* bp = bB + nt * 8 * HSTR;
            uint32_t b0 = *reinterpret_cast<const uint32_t*>(&bp[k0 + 2 * t4]);
            uint32_t b1 = *reinterpret_cast<const uint32_t*>(&bp[k0 + 8 + 2 * t4]);
            mma16816(acc[0][nt], a[0], b0, b1);
            mma16816(acc[1][nt], a[1], b0, b1);
        }
    }

    #pragma unroll
    for (int mt = 0; mt < 2; mt++) {
        int r0 = m0 + wm + mt * 16 + g;
        int r1 = r0 + 8;
        #pragma unroll
        for (int nt = 0; nt < 4; nt++) {
            int col = n0 + wn + nt * 8 + 2 * t4;
            if (r0 < M)
                *reinterpret_cast<uint32_t*>(&P[(size_t)r0 * 256 + col]) =
                    h2u(__floats2half2_rn(acc[mt][nt][0], acc[mt][nt][1]));
            if (r1 < M)
                *reinterpret_cast<uint32_t*>(&P[(size_t)r1 * 256 + col]) =
                    h2u(__floats2half2_rn(acc[mt][nt][2], acc[mt][nt][3]));
        }
    }

    // fp16 hidden copy (nb==0 CTA streams it from the smem stage)
    if (nb == 0) {
        #pragma unroll
        for (int i = tid; i < 128 * 16; i += 256) {
            int row = i >> 4, c8 = i & 15;
            int gr = m0 + row;
            if (gr < M)
                *reinterpret_cast<uint4*>(&P[(size_t)gr * 256 + 128 + c8 * 8]) =
                    *reinterpret_cast<const uint4*>(&sA[row * HSTR + c8 * 8]);
        }
    }
}

// ================= GEMM2: out(fp32) = mask*relu(agg @ Wf^T + bf), W fp16 hi/lo x2 =================
#define SM2_BYTES ((128 + 128) * HSTR * 2)  // 69,632 B
__global__ __launch_bounds__(256, 2)
void gemm_h2(const float* __restrict__ A, const __half* __restrict__ Wh,
             const __half* __restrict__ Wl, const float* __restrict__ bias,
             const int* __restrict__ deg, float* __restrict__ C, int M)
{
    extern __shared__ __half smh[];
    __half* sA  = smh;                  // 128 x HSTR
    __half* sWh = smh + 128 * HSTR;     // 64 x HSTR
    __half* sWl = smh + 192 * HSTR;     // 64 x HSTR

    const int tid = threadIdx.x;
    const int mb = blockIdx.x >> 1;
    const int nb = blockIdx.x & 1;
    const int m0 = mb * 128;
    const int n0 = nb * 64;

    const float4* A4 = reinterpret_cast<const float4*>(A);
    #pragma unroll
    for (int i = tid; i < 128 * 32; i += 256) {
        int row = i >> 5, c4 = i & 31;
        int gr = m0 + row;
        float4 v = make_float4(0.f, 0.f, 0.f, 0.f);
        if (gr < M) v = A4[(size_t)gr * 32 + c4];
        uint2 u = make_uint2(h2u(__floats2half2_rn(v.x, v.y)),
                             h2u(__floats2half2_rn(v.z, v.w)));
        *reinterpret_cast<uint2*>(&sA[row * HSTR + c4 * 4]) = u;
    }
    const uint4* WH4 = reinterpret_cast<const uint4*>(Wh);
    const uint4* WL4 = reinterpret_cast<const uint4*>(Wl);
    #pragma unroll
    for (int i = tid; i < 64 * 16; i += 256) {
        int row = i >> 4, c8 = i & 15;
        *reinterpret_cast<uint4*>(&sWh[row * HSTR + c8 * 8]) = WH4[(size_t)(n0 + row) * 16 + c8];
        *reinterpret_cast<uint4*>(&sWl[row * HSTR + c8 * 8]) = WL4[(size_t)(n0 + row) * 16 + c8];
    }
    __syncthreads();

    const int lane = tid & 31;
    const int wid = tid >> 5;
    const int g = lane >> 2;
    const int t4 = lane & 3;
    const int wm = (wid >> 1) * 32;
    const int wn = (wid & 1) * 32;

    const __half* aB  = sA  + (wm + g) * HSTR;
    const __half* bhB = sWh + (wn + g) * HSTR;
    const __half* blB = sWl + (wn + g) * HSTR;

    float acc[2][4][4];
    #pragma unroll
    for (int mt = 0; mt < 2; mt++)
        #pragma unroll
        for (int nt = 0; nt < 4; nt++)
            #pragma unroll
            for (int q = 0; q < 4; q++) acc[mt][nt][q] = 0.f;

    #pragma unroll
    for (int ks = 0; ks < 8; ks++) {
        const int k0 = ks * 16;
        uint32_t a[2][4];
        #pragma unroll
        for (int mt = 0; mt < 2; mt++) {
            const __half* b = aB + mt * 16 * HSTR;
            a[mt][0] = *reinterpret_cast<const uint32_t*>(&b[k0 + 2 * t4]);
            a[mt][1] = *reinterpret_cast<const uint32_t*>(&b[8 * HSTR + k0 + 2 * t4]);
            a[mt][2] = *reinterpret_cast<const uint32_t*>(&b[k0 + 8 + 2 * t4]);
            a[mt][3] = *reinterpret_cast<const uint32_t*>(&b[8 * HSTR + k0 + 8 + 2 * t4]);
        }
        #pragma unroll
        for (int nt = 0; nt < 4; nt++) {
            const __half* bh = bhB + nt * 8 * HSTR;
            const __half* bl = blB + nt * 8 * HSTR;
            uint32_t bh0 = *reinterpret_cast<const uint32_t*>(&bh[k0 + 2 * t4]);
            uint32_t bh1 = *reinterpret_cast<const uint32_t*>(&bh[k0 + 8 + 2 * t4]);
            uint32_t bl0 = *reinterpret_cast<const uint32_t*>(&bl[k0 + 2 * t4]);
            uint32_t bl1 = *reinterpret_cast<const uint32_t*>(&bl[k0 + 8 + 2 * t4]);
            #pragma unroll
            for (int mt = 0; mt < 2; mt++) {
                mma16816(acc[mt][nt], a[mt], bh0, bh1);
                mma16816(acc[mt][nt], a[mt], bl0, bl1);
            }
        }
    }

    #pragma unroll
    for (int mt = 0; mt < 2; mt++) {
        int r0 = m0 + wm + mt * 16 + g;
        int r1 = r0 + 8;
        bool k0ok = r0 < M, k1ok = r1 < M;
        bool keep0 = k0ok && deg[r0] > 0;
        bool keep1 = k1ok && deg[r1] > 0;
        #pragma unroll
        for (int nt = 0; nt < 4; nt++) {
            int col = n0 + wn + nt * 8 + 2 * t4;
            float b0 = bias[col], b1 = bias[col + 1];
            float c0 = keep0 ? fmaxf(acc[mt][nt][0] + b0, 0.f) : 0.f;
            float c1 = keep0 ? fmaxf(acc[mt][nt][1] + b1, 0.f) : 0.f;
            float c2 = keep1 ? fmaxf(acc[mt][nt][2] + b0, 0.f) : 0.f;
            float c3 = keep1 ? fmaxf(acc[mt][nt][3] + b1, 0.f) : 0.f;
            if (k0ok) *reinterpret_cast<float2*>(C + (size_t)r0 * DD + col) = make_float2(c0, c1);
            if (k1ok) *reinterpret_cast<float2*>(C + (size_t)r1 * DD + col) = make_float2(c2, c3);
        }
    }
}

// -------- edge kernel: THREE edges per warp; packed row gathers --------
__global__ __launch_bounds__(256)
void edge_kernel(const int4* __restrict__ edges, const float* __restrict__ Wattn,
                 const float* __restrict__ rela, int E)
{
    const int base = blockIdx.x * 24 + (threadIdx.x >> 5) * 3;
    const int lane = threadIdx.x & 31;
    const int c = lane * 4;
    const float4 wa = *reinterpret_cast<const float4*>(Wattn + c);

    int4 ed[3];
    bool v[3];
    #pragma unroll
    for (int j = 0; j < 3; j++) {
        v[j] = base + j < E;
        ed[j] = v[j] ? edges[base + j] : make_int4(0, 0, 0, 0);
    }

    // all gathers up front: packed rows (Hs fp16 | hidden fp16), Rr, Qq, rela
    uint2 hs[3], hh[3];
    float4 rr[3], qq[3], mr[3];
    #pragma unroll
    for (int j = 0; j < 3; j++) {
        const __half* prow = g_pack + (size_t)ed[j].y * 256;
        hs[j] = *reinterpret_cast<const uint2*>(prow + c);
        hh[j] = *reinterpret_cast<const uint2*>(prow + 128 + c);
        rr[j] = *reinterpret_cast<const float4*>(g_Rr + (size_t)ed[j].z * DD + c);
        qq[j] = *reinterpret_cast<const float4*>(g_Qq + (size_t)ed[j].x * DD + c);
        mr[j] = *reinterpret_cast<const float4*>(rela + (size_t)ed[j].z * DD + c);
    }

    float p[3];
    #pragma unroll
    for (int j = 0; j < 3; j++) {
        float2 a = __half22float2(*reinterpret_cast<const __half2*>(&hs[j].x));
        float2 b = __half22float2(*reinterpret_cast<const __half2*>(&hs[j].y));
        p[j] = fmaxf(a.x + rr[j].x + qq[j].x, 0.f) * wa.x
             + fmaxf(a.y + rr[j].y + qq[j].y, 0.f) * wa.y
             + fmaxf(b.x + rr[j].z + qq[j].z, 0.f) * wa.z
             + fmaxf(b.y + rr[j].w + qq[j].w, 0.f) * wa.w;
    }
    #pragma unroll
    for (int o = 16; o > 0; o >>= 1) {
        #pragma unroll
        for (int j = 0; j < 3; j++) p[j] += __shfl_xor_sync(0xffffffffu, p[j], o);
    }

    #pragma unroll
    for (int j = 0; j < 3; j++) {
        if (!v[j]) continue;
        float alpha = 1.f / (1.f + __expf(-p[j]));
        float2 ha = __half22float2(*reinterpret_cast<const __half2*>(&hh[j].x));
        float2 hb = __half22float2(*reinterpret_cast<const __half2*>(&hh[j].y));
        float* dst = g_agg + (size_t)ed[j].w * DD + c;
        asm volatile("red.global.add.v4.f32 [%0], {%1,%2,%3,%4};"
                     :: "l"(dst),
                        "f"(ha.x * mr[j].x * alpha), "f"(ha.y * mr[j].y * alpha),
                        "f"(hb.x * mr[j].z * alpha), "f"(hb.y * mr[j].w * alpha) : "memory");
        if (lane == 0) g_deg[ed[j].w] = 1;
    }
}

// -------- launch --------
extern "C" void kernel_launch(void* const* d_in, const int* in_sizes, int n_in,
                              void* d_out, int out_size)
{
    const float* query  = (const float*)d_in[0];
    const float* hidden = (const float*)d_in[3];
    const int*   edges  = (const int*)d_in[4];
    const float* Ws     = (const float*)d_in[6];
    const float* Wr     = (const float*)d_in[7];
    const float* Wqr    = (const float*)d_in[8];
    const float* Wqr_b  = (const float*)d_in[9];
    const float* Wattn  = (const float*)d_in[10];
    const float* rela   = (const float*)d_in[11];
    const float* mlp1_w = (const float*)d_in[12];
    const float* mlp1_b = (const float*)d_in[13];
    const float* mlp2_w = (const float*)d_in[14];
    const float* mlp2_b = (const float*)d_in[15];

    int M = in_sizes[3] / DD;     // B*N = 200000
    int E = in_sizes[4] / 4;      // 600000
    int R = in_sizes[11] / DD;    // 200
    int B = in_sizes[0] / DD;     // 4

    void *aggp = 0, *degp = 0, *packp = 0, *bfp = 0, *wshp = 0, *wfhp = 0, *wflp = 0;
    cudaGetSymbolAddress(&aggp,  g_agg);
    cudaGetSymbolAddress(&degp,  g_deg);
    cudaGetSymbolAddress(&packp, g_pack);
    cudaGetSymbolAddress(&bfp,   g_bf);
    cudaGetSymbolAddress(&wshp,  g_WsH);
    cudaGetSymbolAddress(&wfhp,  g_WfH);
    cudaGetSymbolAddress(&wflp,  g_WfL);

    cudaMemsetAsync(aggp, 0, (size_t)M * DD * sizeof(float), 0);
    cudaMemsetAsync(degp, 0, (size_t)M * sizeof(int), 0);

    prep_kernel<<<DD + R + B, DD>>>(mlp1_w, mlp1_b, mlp2_w, mlp2_b,
                                    rela, Wr, query, Wqr, Wqr_b, R);
    convert_kernel<<<(DD * DD + 255) / 256, 256>>>(Ws);

    cudaFuncSetAttribute(gemm_h1, cudaFuncAttributeMaxDynamicSharedMemorySize, SM1_BYTES);
    cudaFuncSetAttribute(gemm_h2, cudaFuncAttributeMaxDynamicSharedMemorySize, SM2_BYTES);
    int grid = ((M + 127) / 128) * 2;

    // pack = [fp16(hidden @ Ws^T) | fp16(hidden)]
    gemm_h1<<<grid, 256, SM1_BYTES>>>(hidden, (const __half*)wshp, (__half*)packp, M);
    // per-edge attention + scatter (3 edges per warp, 24 per block)
    edge_kernel<<<(E + 23) / 24, 256>>>((const int4*)edges, Wattn, rela, E);
    // out = mask(deg) * relu(agg @ Wf^T + bf)
    gemm_h2<<<grid, 256, SM2_BYTES>>>((const float*)aggp, (const __half*)wfhp,
                                      (const __half*)wflp, (const float*)bfp,
                                      (const int*)degp, (float*)d_out, M);
}

// round 16
// speedup vs baseline: 1.0947x; 1.0370x over previous
#include <cuda_runtime.h>
#include <cuda_fp16.h>
#include <cstdint>

#define DD 128
#define HSTR 136                 // smem half-row stride (136 halves = 272B ≡ 4 banks)
#define MAXM 200000
#define MAXR 256
#define MAXB 8

// -------- scratch (static device memory; no allocs allowed) --------
__device__ __half g_pack[(size_t)MAXM * 256]; // per row: [0:128)=Hs fp16, [128:256)=hidden fp16
__device__ float  g_agg[(size_t)MAXM * DD];   // segment_sum output (102.4 MB)
__device__ int    g_deg[MAXM];                // receive flags
__device__ float  g_Rr[MAXR * DD];            // rela_embed @ Wr^T
__device__ float  g_Qq[MAXB * DD];            // query @ Wqr^T + b
__device__ float  g_Wf[DD * DD];              // mlp2 @ mlp1, natural [n][k]
__device__ float  g_bf[DD];                   // mlp2 @ b1 + b2
__device__ __half g_WsH[DD * DD];             // fp16(Ws_attn_w) [n][k]
__device__ __half g_WfH[DD * DD];             // fp16 hi part of Wf [n][k]
__device__ __half g_WfL[DD * DD];             // fp16 lo part of Wf [n][k]

__device__ __forceinline__ uint32_t h2u(__half2 h) {
    return *reinterpret_cast<uint32_t*>(&h);
}

// m16n8k16 f16 MMA, f32 accum (baseline PTX sm_80+)
__device__ __forceinline__ void mma16816(float* d, const uint32_t* a, uint32_t b0, uint32_t b1) {
    asm volatile(
        "mma.sync.aligned.m16n8k16.row.col.f32.f16.f16.f32 "
        "{%0,%1,%2,%3}, {%4,%5,%6,%7}, {%8,%9}, {%0,%1,%2,%3};"
        : "+f"(d[0]), "+f"(d[1]), "+f"(d[2]), "+f"(d[3])
        : "r"(a[0]), "r"(a[1]), "r"(a[2]), "r"(a[3]), "r"(b0), "r"(b1));
}

// ================= prep: Wf (natural [n][k]), bf, Rr, Qq =================
__global__ void prep_kernel(const float* __restrict__ mlp1_w, const float* __restrict__ mlp1_b,
                            const float* __restrict__ mlp2_w, const float* __restrict__ mlp2_b,
                            const float* __restrict__ rela,   const float* __restrict__ Wr,
                            const float* __restrict__ query,  const float* __restrict__ Wqr,
                            const float* __restrict__ Wqr_b,  int R)
{
    int t = threadIdx.x;
    int bx = blockIdx.x;
    if (bx < DD) {
        int i = bx;
        float acc = 0.f;
        for (int j = 0; j < DD; j++) acc += mlp2_w[i * DD + j] * mlp1_w[j * DD + t];
        g_Wf[i * DD + t] = acc;
        __shared__ float s[DD];
        s[t] = mlp2_w[i * DD + t] * mlp1_b[t];
        __syncthreads();
        if (t == 0) {
            float b = 0.f;
            for (int j = 0; j < DD; j++) b += s[j];
            g_bf[i] = b + mlp2_b[i];
        }
    } else if (bx < DD + R) {
        int r = bx - DD;
        float acc = 0.f;
        for (int d = 0; d < DD; d++) acc += rela[r * DD + d] * Wr[t * DD + d];
        g_Rr[r * DD + t] = acc;
    } else {
        int b = bx - DD - R;
        float acc = Wqr_b[t];
        for (int d = 0; d < DD; d++) acc += query[b * DD + d] * Wqr[t * DD + d];
        g_Qq[b * DD + t] = acc;
    }
}

// convert Ws -> fp16; Wf -> fp16 hi/lo split
__global__ void convert_kernel(const float* __restrict__ Ws) {
    int i = blockIdx.x * 256 + threadIdx.x;
    if (i >= DD * DD) return;
    g_WsH[i] = __float2half_rn(Ws[i]);
    float w = g_Wf[i];
    __half h = __float2half_rn(w);
    g_WfH[i] = h;
    g_WfL[i] = __float2half_rn(w - __half2float(h));
}

// ================= GEMM1: pack = [fp16(hidden @ Ws^T) | fp16(hidden)] =================
// FULL tile 128m x 128n, one CTA per m-tile (A loaded ONCE).
// 8 warps: warp grid 4m x 2n; warp tile 32m x 64n = 2 mtiles x 8 ntiles m16n8k16.
// smem = (128 + 128) * HSTR * 2 = 69,632 B -> 2 CTAs/SM.
#define SM1_BYTES ((128 + 128) * HSTR * 2)
__global__ __launch_bounds__(256, 2)
void gemm_h1(const float* __restrict__ A, const __half* __restrict__ W,
             __half* __restrict__ P, int M)
{
    extern __shared__ __half smh[];
    __half* sA = smh;                  // 128 x HSTR
    __half* sW = smh + 128 * HSTR;     // 128 x HSTR

    const int tid = threadIdx.x;
    const int m0 = blockIdx.x * 128;

    const float4* A4 = reinterpret_cast<const float4*>(A);
    #pragma unroll
    for (int i = tid; i < 128 * 32; i += 256) {
        int row = i >> 5, c4 = i & 31;
        int gr = m0 + row;
        float4 v = make_float4(0.f, 0.f, 0.f, 0.f);
        if (gr < M) v = A4[(size_t)gr * 32 + c4];
        uint2 u = make_uint2(h2u(__floats2half2_rn(v.x, v.y)),
                             h2u(__floats2half2_rn(v.z, v.w)));
        *reinterpret_cast<uint2*>(&sA[row * HSTR + c4 * 4]) = u;
    }
    const uint4* W4 = reinterpret_cast<const uint4*>(W);
    #pragma unroll
    for (int i = tid; i < 128 * 16; i += 256) {
        int row = i >> 4, c8 = i & 15;
        *reinterpret_cast<uint4*>(&sW[row * HSTR + c8 * 8]) = W4[(size_t)row * 16 + c8];
    }
    __syncthreads();

    const int lane = tid & 31;
    const int wid = tid >> 5;
    const int g = lane >> 2;
    const int t4 = lane & 3;
    const int wm = (wid >> 1) * 32;    // 4 m positions: 0,32,64,96
    const int wn = (wid & 1) * 64;     // 2 n positions: 0,64

    const __half* aB = sA + (wm + g) * HSTR;
    const __half* bB = sW + (wn + g) * HSTR;

    float acc[2][8][4];
    #pragma unroll
    for (int mt = 0; mt < 2; mt++)
        #pragma unroll
        for (int nt = 0; nt < 8; nt++)
            #pragma unroll
            for (int q = 0; q < 4; q++) acc[mt][nt][q] = 0.f;

    #pragma unroll
    for (int ks = 0; ks < 8; ks++) {
        const int k0 = ks * 16;
        uint32_t a[2][4];
        #pragma unroll
        for (int mt = 0; mt < 2; mt++) {
            const __half* b = aB + mt * 16 * HSTR;
            a[mt][0] = *reinterpret_cast<const uint32_t*>(&b[k0 + 2 * t4]);
            a[mt][1] = *reinterpret_cast<const uint32_t*>(&b[8 * HSTR + k0 + 2 * t4]);
            a[mt][2] = *reinterpret_cast<const uint32_t*>(&b[k0 + 8 + 2 * t4]);
            a[mt][3] = *reinterpret_cast<const uint32_t*>(&b[8 * HSTR + k0 + 8 + 2 * t4]);
        }
        #pragma unroll
        for (int nt = 0; nt < 8; nt++) {
            const __half* bp = bB + nt * 8 * HSTR;
            uint32_t b0 = *reinterpret_cast<const uint32_t*>(&bp[k0 + 2 * t4]);
            uint32_t b1 = *reinterpret_cast<const uint32_t*>(&bp[k0 + 8 + 2 * t4]);
            mma16816(acc[0][nt], a[0], b0, b1);
            mma16816(acc[1][nt], a[1], b0, b1);
        }
    }

    #pragma unroll
    for (int mt = 0; mt < 2; mt++) {
        int r0 = m0 + wm + mt * 16 + g;
        int r1 = r0 + 8;
        #pragma unroll
        for (int nt = 0; nt < 8; nt++) {
            int col = wn + nt * 8 + 2 * t4;
            if (r0 < M)
                *reinterpret_cast<uint32_t*>(&P[(size_t)r0 * 256 + col]) =
                    h2u(__floats2half2_rn(acc[mt][nt][0], acc[mt][nt][1]));
            if (r1 < M)
                *reinterpret_cast<uint32_t*>(&P[(size_t)r1 * 256 + col]) =
                    h2u(__floats2half2_rn(acc[mt][nt][2], acc[mt][nt][3]));
        }
    }

    // fp16 hidden copy from the smem stage
    #pragma unroll
    for (int i = tid; i < 128 * 16; i += 256) {
        int row = i >> 4, c8 = i & 15;
        int gr = m0 + row;
        if (gr < M)
            *reinterpret_cast<uint4*>(&P[(size_t)gr * 256 + 128 + c8 * 8]) =
                *reinterpret_cast<const uint4*>(&sA[row * HSTR + c8 * 8]);
    }
}

// ================= GEMM2: out(fp32) = mask*relu(agg @ Wf^T + bf), W fp16 hi/lo x2 =================
#define SM2_BYTES ((128 + 128) * HSTR * 2)  // 69,632 B
__global__ __launch_bounds__(256, 2)
void gemm_h2(const float* __restrict__ A, const __half* __restrict__ Wh,
             const __half* __restrict__ Wl, const float* __restrict__ bias,
             const int* __restrict__ deg, float* __restrict__ C, int M)
{
    extern __shared__ __half smh[];
    __half* sA  = smh;                  // 128 x HSTR
    __half* sWh = smh + 128 * HSTR;     // 64 x HSTR
    __half* sWl = smh + 192 * HSTR;     // 64 x HSTR

    const int tid = threadIdx.x;
    const int mb = blockIdx.x >> 1;
    const int nb = blockIdx.x & 1;
    const int m0 = mb * 128;
    const int n0 = nb * 64;

    const float4* A4 = reinterpret_cast<const float4*>(A);
    #pragma unroll
    for (int i = tid; i < 128 * 32; i += 256) {
        int row = i >> 5, c4 = i & 31;
        int gr = m0 + row;
        float4 v = make_float4(0.f, 0.f, 0.f, 0.f);
        if (gr < M) v = A4[(size_t)gr * 32 + c4];
        uint2 u = make_uint2(h2u(__floats2half2_rn(v.x, v.y)),
                             h2u(__floats2half2_rn(v.z, v.w)));
        *reinterpret_cast<uint2*>(&sA[row * HSTR + c4 * 4]) = u;
    }
    const uint4* WH4 = reinterpret_cast<const uint4*>(Wh);
    const uint4* WL4 = reinterpret_cast<const uint4*>(Wl);
    #pragma unroll
    for (int i = tid; i < 64 * 16; i += 256) {
        int row = i >> 4, c8 = i & 15;
        *reinterpret_cast<uint4*>(&sWh[row * HSTR + c8 * 8]) = WH4[(size_t)(n0 + row) * 16 + c8];
        *reinterpret_cast<uint4*>(&sWl[row * HSTR + c8 * 8]) = WL4[(size_t)(n0 + row) * 16 + c8];
    }
    __syncthreads();

    const int lane = tid & 31;
    const int wid = tid >> 5;
    const int g = lane >> 2;
    const int t4 = lane & 3;
    const int wm = (wid >> 1) * 32;
    const int wn = (wid & 1) * 32;

    const __half* aB  = sA  + (wm + g) * HSTR;
    const __half* bhB = sWh + (wn + g) * HSTR;
    const __half* blB = sWl + (wn + g) * HSTR;

    float acc[2][4][4];
    #pragma unroll
    for (int mt = 0; mt < 2; mt++)
        #pragma unroll
        for (int nt = 0; nt < 4; nt++)
            #pragma unroll
            for (int q = 0; q < 4; q++) acc[mt][nt][q] = 0.f;

    #pragma unroll
    for (int ks = 0; ks < 8; ks++) {
        const int k0 = ks * 16;
        uint32_t a[2][4];
        #pragma unroll
        for (int mt = 0; mt < 2; mt++) {
            const __half* b = aB + mt * 16 * HSTR;
            a[mt][0] = *reinterpret_cast<const uint32_t*>(&b[k0 + 2 * t4]);
            a[mt][1] = *reinterpret_cast<const uint32_t*>(&b[8 * HSTR + k0 + 2 * t4]);
            a[mt][2] = *reinterpret_cast<const uint32_t*>(&b[k0 + 8 + 2 * t4]);
            a[mt][3] = *reinterpret_cast<const uint32_t*>(&b[8 * HSTR + k0 + 8 + 2 * t4]);
        }
        #pragma unroll
        for (int nt = 0; nt < 4; nt++) {
            const __half* bh = bhB + nt * 8 * HSTR;
            const __half* bl = blB + nt * 8 * HSTR;
            uint32_t bh0 = *reinterpret_cast<const uint32_t*>(&bh[k0 + 2 * t4]);
            uint32_t bh1 = *reinterpret_cast<const uint32_t*>(&bh[k0 + 8 + 2 * t4]);
            uint32_t bl0 = *reinterpret_cast<const uint32_t*>(&bl[k0 + 2 * t4]);
            uint32_t bl1 = *reinterpret_cast<const uint32_t*>(&bl[k0 + 8 + 2 * t4]);
            #pragma unroll
            for (int mt = 0; mt < 2; mt++) {
                mma16816(acc[mt][nt], a[mt], bh0, bh1);
                mma16816(acc[mt][nt], a[mt], bl0, bl1);
            }
        }
    }

    #pragma unroll
    for (int mt = 0; mt < 2; mt++) {
        int r0 = m0 + wm + mt * 16 + g;
        int r1 = r0 + 8;
        bool k0ok = r0 < M, k1ok = r1 < M;
        bool keep0 = k0ok && deg[r0] > 0;
        bool keep1 = k1ok && deg[r1] > 0;
        #pragma unroll
        for (int nt = 0; nt < 4; nt++) {
            int col = n0 + wn + nt * 8 + 2 * t4;
            float b0 = bias[col], b1 = bias[col + 1];
            float c0 = keep0 ? fmaxf(acc[mt][nt][0] + b0, 0.f) : 0.f;
            float c1 = keep0 ? fmaxf(acc[mt][nt][1] + b1, 0.f) : 0.f;
            float c2 = keep1 ? fmaxf(acc[mt][nt][2] + b0, 0.f) : 0.f;
            float c3 = keep1 ? fmaxf(acc[mt][nt][3] + b1, 0.f) : 0.f;
            if (k0ok) *reinterpret_cast<float2*>(C + (size_t)r0 * DD + col) = make_float2(c0, c1);
            if (k1ok) *reinterpret_cast<float2*>(C + (size_t)r1 * DD + col) = make_float2(c2, c3);
        }
    }
}

// -------- edge kernel: TWO edges per warp (R14 config — best measured) --------
__global__ __launch_bounds__(256)
void edge_kernel(const int4* __restrict__ edges, const float* __restrict__ Wattn,
                 const float* __restrict__ rela, int E)
{
    const int base = blockIdx.x * 16 + ((threadIdx.x >> 5) << 1);
    const int lane = threadIdx.x & 31;
    const int c = lane * 4;
    const bool v0 = base < E;
    const bool v1 = base + 1 < E;
    const int4 ed0 = v0 ? edges[base]     : make_int4(0, 0, 0, 0);
    const int4 ed1 = v1 ? edges[base + 1] : make_int4(0, 0, 0, 0);

    const __half* p0 = g_pack + (size_t)ed0.y * 256;
    const __half* p1 = g_pack + (size_t)ed1.y * 256;
    uint2 hs0 = *reinterpret_cast<const uint2*>(p0 + c);
    uint2 hs1 = *reinterpret_cast<const uint2*>(p1 + c);
    uint2 hh0 = *reinterpret_cast<const uint2*>(p0 + 128 + c);
    uint2 hh1 = *reinterpret_cast<const uint2*>(p1 + 128 + c);
    float4 rr0 = *reinterpret_cast<const float4*>(g_Rr + (size_t)ed0.z * DD + c);
    float4 rr1 = *reinterpret_cast<const float4*>(g_Rr + (size_t)ed1.z * DD + c);
    float4 mr0 = *reinterpret_cast<const float4*>(rela + (size_t)ed0.z * DD + c);
    float4 mr1 = *reinterpret_cast<const float4*>(rela + (size_t)ed1.z * DD + c);
    float4 qq0 = *reinterpret_cast<const float4*>(g_Qq + (size_t)ed0.x * DD + c);
    float4 qq1 = *reinterpret_cast<const float4*>(g_Qq + (size_t)ed1.x * DD + c);
    float4 wa  = *reinterpret_cast<const float4*>(Wattn + c);

    float2 a0 = __half22float2(*reinterpret_cast<const __half2*>(&hs0.x));
    float2 b0 = __half22float2(*reinterpret_cast<const __half2*>(&hs0.y));
    float2 a1 = __half22float2(*reinterpret_cast<const __half2*>(&hs1.x));
    float2 b1 = __half22float2(*reinterpret_cast<const __half2*>(&hs1.y));

    float pp0 = fmaxf(a0.x + rr0.x + qq0.x, 0.f) * wa.x
              + fmaxf(a0.y + rr0.y + qq0.y, 0.f) * wa.y
              + fmaxf(b0.x + rr0.z + qq0.z, 0.f) * wa.z
              + fmaxf(b0.y + rr0.w + qq0.w, 0.f) * wa.w;
    float pp1 = fmaxf(a1.x + rr1.x + qq1.x, 0.f) * wa.x
              + fmaxf(a1.y + rr1.y + qq1.y, 0.f) * wa.y
              + fmaxf(b1.x + rr1.z + qq1.z, 0.f) * wa.z
              + fmaxf(b1.y + rr1.w + qq1.w, 0.f) * wa.w;
    #pragma unroll
    for (int o = 16; o > 0; o >>= 1) {
        pp0 += __shfl_xor_sync(0xffffffffu, pp0, o);
        pp1 += __shfl_xor_sync(0xffffffffu, pp1, o);
    }
    float alpha0 = 1.f / (1.f + __expf(-pp0));
    float alpha1 = 1.f / (1.f + __expf(-pp1));

    if (v0) {
        float2 ha = __half22float2(*reinterpret_cast<const __half2*>(&hh0.x));
        float2 hb = __half22float2(*reinterpret_cast<const __half2*>(&hh0.y));
        float* dst = g_agg + (size_t)ed0.w * DD + c;
        asm volatile("red.global.add.v4.f32 [%0], {%1,%2,%3,%4};"
                     :: "l"(dst),
                        "f"(ha.x * mr0.x * alpha0), "f"(ha.y * mr0.y * alpha0),
                        "f"(hb.x * mr0.z * alpha0), "f"(hb.y * mr0.w * alpha0) : "memory");
        if (lane == 0) g_deg[ed0.w] = 1;
    }
    if (v1) {
        float2 ha = __half22float2(*reinterpret_cast<const __half2*>(&hh1.x));
        float2 hb = __half22float2(*reinterpret_cast<const __half2*>(&hh1.y));
        float* dst = g_agg + (size_t)ed1.w * DD + c;
        asm volatile("red.global.add.v4.f32 [%0], {%1,%2,%3,%4};"
                     :: "l"(dst),
                        "f"(ha.x * mr1.x * alpha1), "f"(ha.y * mr1.y * alpha1),
                        "f"(hb.x * mr1.z * alpha1), "f"(hb.y * mr1.w * alpha1) : "memory");
        if (lane == 0) g_deg[ed1.w] = 1;
    }
}

// -------- launch --------
extern "C" void kernel_launch(void* const* d_in, const int* in_sizes, int n_in,
                              void* d_out, int out_size)
{
    const float* query  = (const float*)d_in[0];
    const float* hidden = (const float*)d_in[3];
    const int*   edges  = (const int*)d_in[4];
    const float* Ws     = (const float*)d_in[6];
    const float* Wr     = (const float*)d_in[7];
    const float* Wqr    = (const float*)d_in[8];
    const float* Wqr_b  = (const float*)d_in[9];
    const float* Wattn  = (const float*)d_in[10];
    const float* rela   = (const float*)d_in[11];
    const float* mlp1_w = (const float*)d_in[12];
    const float* mlp1_b = (const float*)d_in[13];
    const float* mlp2_w = (const float*)d_in[14];
    const float* mlp2_b = (const float*)d_in[15];

    int M = in_sizes[3] / DD;     // B*N = 200000
    int E = in_sizes[4] / 4;      // 600000
    int R = in_sizes[11] / DD;    // 200
    int B = in_sizes[0] / DD;     // 4

    void *aggp = 0, *degp = 0, *packp = 0, *bfp = 0, *wshp = 0, *wfhp = 0, *wflp = 0;
    cudaGetSymbolAddress(&aggp,  g_agg);
    cudaGetSymbolAddress(&degp,  g_deg);
    cudaGetSymbolAddress(&packp, g_pack);
    cudaGetSymbolAddress(&bfp,   g_bf);
    cudaGetSymbolAddress(&wshp,  g_WsH);
    cudaGetSymbolAddress(&wfhp,  g_WfH);
    cudaGetSymbolAddress(&wflp,  g_WfL);

    cudaMemsetAsync(aggp, 0, (size_t)M * DD * sizeof(float), 0);
    cudaMemsetAsync(degp, 0, (size_t)M * sizeof(int), 0);

    prep_kernel<<<DD + R + B, DD>>>(mlp1_w, mlp1_b, mlp2_w, mlp2_b,
                                    rela, Wr, query, Wqr, Wqr_b, R);
    convert_kernel<<<(DD * DD + 255) / 256, 256>>>(Ws);

    cudaFuncSetAttribute(gemm_h1, cudaFuncAttributeMaxDynamicSharedMemorySize, SM1_BYTES);
    cudaFuncSetAttribute(gemm_h2, cudaFuncAttributeMaxDynamicSharedMemorySize, SM2_BYTES);

    // pack = [fp16(hidden @ Ws^T) | fp16(hidden)]  (full 128x128 tile, A loaded once)
    gemm_h1<<<(M + 127) / 128, 256, SM1_BYTES>>>(hidden, (const __half*)wshp, (__half*)packp, M);
    // per-edge attention + scatter (2 edges per warp)
    edge_kernel<<<(E + 15) / 16, 256>>>((const int4*)edges, Wattn, rela, E);
    // out = mask(deg) * relu(agg @ Wf^T + bf)
    gemm_h2<<<((M + 127) / 128) * 2, 256, SM2_BYTES>>>((const float*)aggp, (const __half*)wfhp,
                                                       (const __half*)wflp, (const float*)bfp,
                                                       (const int*)degp, (float*)d_out, M);
}